// round 16
// baseline (speedup 1.0000x reference)
#include <cuda_runtime.h>
#include <cuda_fp16.h>
#include <cstdint>

// B tiles in dynamic smem, 144-byte row pitch (conflict-free ldmatrix)
#define BH_OFF 0u
#define BL_OFF 9216u
#define DSMEM  18432

#define LDSM4(r0, r1, r2, r3, a) \
    asm volatile("ldmatrix.sync.aligned.m8n8.x4.shared.b16 {%0,%1,%2,%3}, [%4];" \
                 : "=r"(r0), "=r"(r1), "=r"(r2), "=r"(r3) : "r"(a))

#define MMAF16(d, a, b0v, b1v) \
    asm volatile("mma.sync.aligned.m16n8k16.row.col.f32.f16.f16.f32 " \
                 "{%0,%1,%2,%3}, {%4,%5,%6,%7}, {%8,%9}, {%0,%1,%2,%3};" \
                 : "+f"(d[0]), "+f"(d[1]), "+f"(d[2]), "+f"(d[3]) \
                 : "r"(a[0]), "r"(a[1]), "r"(a[2]), "r"(a[3]), "r"(b0v), "r"(b1v))

__global__ void __launch_bounds__(128, 4) netc_kernel(
    const float* __restrict__ x, const float* __restrict__ y,
    const float* __restrict__ ex, const float* __restrict__ ey,
    const float* __restrict__ W1, const float* __restrict__ b1,
    const float* __restrict__ W2, const float* __restrict__ b2,
    const float* __restrict__ W3, const float* __restrict__ b3,
    float* __restrict__ out, int n, int ntiles) {
    extern __shared__ char dsm[];
    __shared__ float b2s[64], w3s[64];
    __shared__ float w1qA[4 * 17], w1qB[4 * 17], b1q[4 * 17];
    __shared__ float usx[128];
    __shared__ float utg_sh;

    unsigned base = (unsigned)__cvta_generic_to_shared(dsm);
    int tid = threadIdx.x;
    int lane = tid & 31, wid = tid >> 5;
    int q = lane & 3, g = lane >> 2;

    if (tid < 64) { b2s[tid] = b2[tid]; w3s[tid] = W3[tid]; }
    if (tid < 64) {
        int qq = tid >> 4, li = tid & 15;
        int kk = (li >> 2) * 16 + ((li >> 1) & 1) * 8 + qq * 2 + (li & 1);
        w1qA[qq * 17 + li] = W1[2 * kk];
        w1qB[qq * 17 + li] = W1[2 * kk + 1];
        b1q[qq * 17 + li] = b1[kk];
    }

    // W2 -> fp16 hi/lo B tiles (once per persistent CTA).
    for (int p = tid; p < 2048; p += 128) {
        int j = p >> 5, kw = p & 31;
        float2 v = ((const float2*)W2)[p];
        __half hx = __float2half_rn(v.x);
        __half hy = __float2half_rn(v.y);
        __half lx = __float2half_rn(v.x - __half2float(hx));
        __half ly = __float2half_rn(v.y - __half2float(hy));
        uint32_t whi = ((uint32_t)__half_as_ushort(hy) << 16) | __half_as_ushort(hx);
        uint32_t wlo = ((uint32_t)__half_as_ushort(ly) << 16) | __half_as_ushort(lx);
        unsigned off = (unsigned)(j * 144 + kw * 4);
        asm volatile("st.shared.b32 [%0], %1;" :: "r"(base + BH_OFF + off), "r"(whi) : "memory");
        asm volatile("st.shared.b32 [%0], %1;" :: "r"(base + BL_OFF + off), "r"(wlo) : "memory");
    }

    // ---- fused u(target): per-CTA, fp32, using usx as scratch ----
    const float TT = 6.2562059f;
    if (tid < 64)
        usx[tid] = fmaxf(fmaf(W1[2 * tid], TT, fmaf(W1[2 * tid + 1], TT, b1[tid])), 0.f);
    __syncthreads();
    if (tid < 64) {
        float acc = b2s[tid];
#pragma unroll
        for (int k = 0; k < 64; k++) acc = fmaf(W2[tid * 64 + k], usx[k], acc);
        usx[64 + tid] = w3s[tid] * fmaxf(acc, 0.f);
    }
    __syncthreads();
    if (tid == 0) {
        float s = 0.f;
#pragma unroll
        for (int k = 0; k < 64; k++) s += usx[64 + k];
        utg_sh = s;   // b3 added later with bias3
    }
    __syncthreads();

    float ut = utg_sh, bias3 = b3[0];
    int b_row = lane & 7, b_coff = (lane >> 3) * 16;
    const float* wAq = &w1qA[q * 17];
    const float* wBq = &w1qB[q * 17];
    const float* bbq = &b1q[q * 17];

    // Preload tile-0 inputs for this lane's 4 fragment token-rows.
    int tile = blockIdx.x;
    float ain[2][2], cin[2][2];
    {
        int tb = tile * 128 + wid * 32 + g;
#pragma unroll
        for (int mt = 0; mt < 2; mt++)
#pragma unroll
            for (int hf = 0; hf < 2; hf++) {
                int idx = min(tb + mt * 16 + hf * 8, n - 1);
                ain[mt][hf] = x[idx] + ex[idx];
                cin[mt][hf] = y[idx] + ey[idx];
            }
    }

    for (; tile < ntiles; tile += gridDim.x) {
        int mytok = tile * 128 + tid;

        // ---- layer 1 + single-fp16 A fragments (weights from smem tables) ----
        uint32_t Ah[2][4][4];
#pragma unroll
        for (int ks = 0; ks < 4; ks++) {
            float wa0 = wAq[ks * 4 + 0], wa1 = wAq[ks * 4 + 1], wa2 = wAq[ks * 4 + 2], wa3 = wAq[ks * 4 + 3];
            float wb0 = wBq[ks * 4 + 0], wb1 = wBq[ks * 4 + 1], wb2 = wBq[ks * 4 + 2], wb3 = wBq[ks * 4 + 3];
            float bb0 = bbq[ks * 4 + 0], bb1 = bbq[ks * 4 + 1], bb2 = bbq[ks * 4 + 2], bb3 = bbq[ks * 4 + 3];
#pragma unroll
            for (int mt = 0; mt < 2; mt++) {
#pragma unroll
                for (int hf = 0; hf < 2; hf++) {
                    float av = ain[mt][hf], cv = cin[mt][hf];
                    float v0 = fmaxf(fmaf(wa0, av, fmaf(wb0, cv, bb0)), 0.f);
                    float v1 = fmaxf(fmaf(wa1, av, fmaf(wb1, cv, bb1)), 0.f);
                    float v2 = fmaxf(fmaf(wa2, av, fmaf(wb2, cv, bb2)), 0.f);
                    float v3 = fmaxf(fmaf(wa3, av, fmaf(wb3, cv, bb3)), 0.f);
                    uint32_t h01, h23;
                    asm("cvt.rn.f16x2.f32 %0, %1, %2;" : "=r"(h01) : "f"(v1), "f"(v0));
                    asm("cvt.rn.f16x2.f32 %0, %1, %2;" : "=r"(h23) : "f"(v3), "f"(v2));
                    Ah[mt][ks][hf] = h01;
                    Ah[mt][ks][2 + hf] = h23;
                }
            }
        }

        // Prefetch next tile's inputs (hidden under the GEMM).
        float na[2][2], nc[2][2];
        int ntile = tile + gridDim.x;
        if (ntile < ntiles) {
            int tb = ntile * 128 + wid * 32 + g;
#pragma unroll
            for (int mt = 0; mt < 2; mt++)
#pragma unroll
                for (int hf = 0; hf < 2; hf++) {
                    int idx = min(tb + mt * 16 + hf * 8, n - 1);
                    na[mt][hf] = x[idx] + ex[idx];
                    nc[mt][hf] = y[idx] + ey[idx];
                }
        } else {
#pragma unroll
            for (int mt = 0; mt < 2; mt++)
#pragma unroll
                for (int hf = 0; hf < 2; hf++) { na[mt][hf] = ain[mt][hf]; nc[mt][hf] = cin[mt][hf]; }
        }

        // ---- GEMM + interleaved layer-3: ntp outer, split inner ----
        float s00 = 0.f, s01 = 0.f, s10 = 0.f, s11 = 0.f;
#pragma unroll
        for (int ntp = 0; ntp < 4; ntp++) {
            int nt0 = 2 * ntp, nt1 = 2 * ntp + 1;
            float d[2][2][4];
#pragma unroll
            for (int mt = 0; mt < 2; mt++)
#pragma unroll
                for (int n2 = 0; n2 < 2; n2++)
#pragma unroll
                    for (int r = 0; r < 4; r++) d[mt][n2][r] = 0.f;

            uint32_t bfrA[8], bfrB[8];
            unsigned rowA = (unsigned)((nt0 * 8 + b_row) * 144) + b_coff;
            unsigned rowB = (unsigned)((nt1 * 8 + b_row) * 144) + b_coff;

            LDSM4(bfrA[0], bfrA[1], bfrA[2], bfrA[3], base + BH_OFF + rowA);
            LDSM4(bfrA[4], bfrA[5], bfrA[6], bfrA[7], base + BH_OFF + rowA + 64);
            LDSM4(bfrB[0], bfrB[1], bfrB[2], bfrB[3], base + BH_OFF + rowB);
            LDSM4(bfrB[4], bfrB[5], bfrB[6], bfrB[7], base + BH_OFF + rowB + 64);
#pragma unroll
            for (int ks = 0; ks < 4; ks++) {
                int bi = (ks >> 1) * 4 + (ks & 1) * 2;
                MMAF16(d[0][0], Ah[0][ks], bfrA[bi], bfrA[bi + 1]);
                MMAF16(d[0][1], Ah[0][ks], bfrB[bi], bfrB[bi + 1]);
                MMAF16(d[1][0], Ah[1][ks], bfrA[bi], bfrA[bi + 1]);
                MMAF16(d[1][1], Ah[1][ks], bfrB[bi], bfrB[bi + 1]);
            }
            LDSM4(bfrA[0], bfrA[1], bfrA[2], bfrA[3], base + BL_OFF + rowA);
            LDSM4(bfrA[4], bfrA[5], bfrA[6], bfrA[7], base + BL_OFF + rowA + 64);
            LDSM4(bfrB[0], bfrB[1], bfrB[2], bfrB[3], base + BL_OFF + rowB);
            LDSM4(bfrB[4], bfrB[5], bfrB[6], bfrB[7], base + BL_OFF + rowB + 64);
#pragma unroll
            for (int ks = 0; ks < 4; ks++) {
                int bi = (ks >> 1) * 4 + (ks & 1) * 2;
                MMAF16(d[0][0], Ah[0][ks], bfrA[bi], bfrA[bi + 1]);
                MMAF16(d[0][1], Ah[0][ks], bfrB[bi], bfrB[bi + 1]);
                MMAF16(d[1][0], Ah[1][ks], bfrA[bi], bfrA[bi + 1]);
                MMAF16(d[1][1], Ah[1][ks], bfrB[bi], bfrB[bi + 1]);
            }

            // layer-3 partial for these 2 n-tiles
#pragma unroll
            for (int n2 = 0; n2 < 2; n2++) {
                int j0 = (nt0 + n2) * 8 + 2 * q, j1 = j0 + 1;
                float w30 = w3s[j0], w31 = w3s[j1];
                float b20 = b2s[j0], b21 = b2s[j1];
                s00 = fmaf(w30, fmaxf(d[0][n2][0] + b20, 0.f), s00);
                s00 = fmaf(w31, fmaxf(d[0][n2][1] + b21, 0.f), s00);
                s01 = fmaf(w30, fmaxf(d[0][n2][2] + b20, 0.f), s01);
                s01 = fmaf(w31, fmaxf(d[0][n2][3] + b21, 0.f), s01);
                s10 = fmaf(w30, fmaxf(d[1][n2][0] + b20, 0.f), s10);
                s10 = fmaf(w31, fmaxf(d[1][n2][1] + b21, 0.f), s10);
                s11 = fmaf(w30, fmaxf(d[1][n2][2] + b20, 0.f), s11);
                s11 = fmaf(w31, fmaxf(d[1][n2][3] + b21, 0.f), s11);
            }
        }

        // ---- reduce over the 4 q-lanes, exchange via smem ----
        s00 += __shfl_xor_sync(0xffffffffu, s00, 1);
        s00 += __shfl_xor_sync(0xffffffffu, s00, 2);
        s01 += __shfl_xor_sync(0xffffffffu, s01, 1);
        s01 += __shfl_xor_sync(0xffffffffu, s01, 2);
        s10 += __shfl_xor_sync(0xffffffffu, s10, 1);
        s10 += __shfl_xor_sync(0xffffffffu, s10, 2);
        s11 += __shfl_xor_sync(0xffffffffu, s11, 1);
        s11 += __shfl_xor_sync(0xffffffffu, s11, 2);
        if (q == 0) {
            usx[wid * 32 + g] = s00;
            usx[wid * 32 + g + 8] = s01;
            usx[wid * 32 + 16 + g] = s10;
            usx[wid * 32 + 16 + g + 8] = s11;
        }
        __syncwarp();

        if (mytok < n) {
            float xv = x[mytok], yv = y[mytok];
            float u = usx[tid] + bias3 - (ut + bias3);  // = usx - ut (bias3 cancels in control)
            float xs = xv * 0.1f, ys = yv * 0.1f;
            float x2 = xs * xs, y2 = ys * ys;
            float ivx = 1.f / (0.25f + x2);
            float ivy = 1.f / (0.25f + y2);
            float hx = x2 * ivx, hy = y2 * ivy;
            float gx = 0.25f * ivx, gy = 0.25f * ivy;
            float dx = 10.f * (hx + 0.2f * gy - 1.1f * xs + u * hx);
            float dy = 10.f * (hy + 0.2f * gx - 1.1f * ys);
            out[mytok] = dx;
            out[n + mytok] = dy;
            out[2 * n + mytok] = -dx;
            out[3 * n + mytok] = -dy;
        }
        __syncwarp();  // usx reuse guard

#pragma unroll
        for (int mt = 0; mt < 2; mt++)
#pragma unroll
            for (int hf = 0; hf < 2; hf++) { ain[mt][hf] = na[mt][hf]; cin[mt][hf] = nc[mt][hf]; }
    }
}

extern "C" void kernel_launch(void* const* d_in, const int* in_sizes, int n_in,
                              void* d_out, int out_size) {
    const float* x  = (const float*)d_in[0];
    const float* y  = (const float*)d_in[1];
    const float* ex = (const float*)d_in[2];
    const float* ey = (const float*)d_in[3];
    const float* W1 = (const float*)d_in[4];
    const float* b1 = (const float*)d_in[5];
    const float* W2 = (const float*)d_in[6];
    const float* b2 = (const float*)d_in[7];
    const float* W3 = (const float*)d_in[8];
    const float* b3 = (const float*)d_in[9];
    int n = in_sizes[0];
    int ntiles = (n + 127) / 128;

    static bool attr_set = false;
    if (!attr_set) {
        cudaFuncSetAttribute(netc_kernel,
                             cudaFuncAttributeMaxDynamicSharedMemorySize, DSMEM);
        attr_set = true;
    }

    int blocks = 592;  // 4 persistent CTAs per SM
    if (blocks > ntiles) blocks = ntiles;
    netc_kernel<<<blocks, 128, DSMEM>>>(x, y, ex, ey, W1, b1, W2, b2, W3, b3,
                                        (float*)d_out, n, ntiles);
}